// round 1
// baseline (speedup 1.0000x reference)
#include <cuda_runtime.h>
#include <math.h>

#define TT 4096
#define HH 2048
#define EE 8
#define II 5632

#define BM 64
#define BN 64
#define BK 16

// ---------------- static device scratch (no allocations allowed) ----------------
__device__ int   g_cnt[EE];                     // tokens routed to each expert
__device__ int   g_tok[EE * TT];                // per-expert token lists
__device__ int   g_slot[TT * 2];                // token -> (e*TT + pos) for its 2 experts
__device__ float g_wt[TT * 2];                  // token -> normalized top-2 weights
__device__ float g_h[(size_t)EE * TT * II];     // silu(g)*u intermediate   (~738 MB)
__device__ float g_y[(size_t)EE * TT * HH];     // per-(expert,pos) outputs (~268 MB)

// ---------------- kernel 1: zero counters ----------------
__global__ void zero_counts_kernel() {
    if (threadIdx.x < EE) g_cnt[threadIdx.x] = 0;
}

// ---------------- kernel 2: gating (warp per token) ----------------
__global__ void gate_kernel(const float* __restrict__ x, const float* __restrict__ gw) {
    int tid  = threadIdx.x;
    int warp = tid >> 5;
    int lane = tid & 31;
    int t = blockIdx.x * 4 + warp;
    if (t >= TT) return;

    const float* xr = x + (size_t)t * HH;
    float acc[EE];
#pragma unroll
    for (int e = 0; e < EE; e++) acc[e] = 0.f;

    for (int h0 = lane * 4; h0 < HH; h0 += 32 * 4) {
        float4 xv = *(const float4*)&xr[h0];
#pragma unroll
        for (int e = 0; e < EE; e++) {
            float4 wv = __ldg((const float4*)&gw[e * HH + h0]);
            acc[e] += xv.x * wv.x + xv.y * wv.y + xv.z * wv.z + xv.w * wv.w;
        }
    }
#pragma unroll
    for (int off = 16; off; off >>= 1) {
#pragma unroll
        for (int e = 0; e < EE; e++)
            acc[e] += __shfl_xor_sync(0xffffffffu, acc[e], off);
    }

    if (lane == 0) {
        // top-2 over logits (softmax is monotone; ties -> lowest index, matches lax.top_k)
        int e0 = 0;
#pragma unroll
        for (int e = 1; e < EE; e++)
            if (acc[e] > acc[e0]) e0 = e;
        int e1 = (e0 == 0) ? 1 : 0;
#pragma unroll
        for (int e = 0; e < EE; e++)
            if (e != e0 && acc[e] > acc[e1]) e1 = e;

        // renormalized top-2 softmax weights: w0 = p0/(p0+p1) = 1/(1+exp(l1-l0))
        float d  = acc[e1] - acc[e0];     // <= 0
        float p1 = expf(d);
        float w0 = 1.f / (1.f + p1);
        float w1 = p1 * w0;

        int pos0 = atomicAdd(&g_cnt[e0], 1);
        int pos1 = atomicAdd(&g_cnt[e1], 1);
        g_tok[e0 * TT + pos0] = t;
        g_tok[e1 * TT + pos1] = t;
        g_slot[t * 2 + 0] = e0 * TT + pos0;
        g_slot[t * 2 + 1] = e1 * TT + pos1;
        g_wt[t * 2 + 0] = w0;
        g_wt[t * 2 + 1] = w1;
    }
}

// ---------------- kernel 3: GEMM1 fused  h = silu(X @ Wg^T) * (X @ Wu^T) ----------------
// grid: (II/BN, TT/BM, EE); block 256
__global__ void __launch_bounds__(256) gemm1_kernel(
    const float* __restrict__ x, const float* __restrict__ w13)
{
    int e   = blockIdx.z;
    int cnt = g_cnt[e];
    int mb  = blockIdx.y;
    if (mb * BM >= cnt) return;
    int nb = blockIdx.x;

    __shared__ __align__(16) float As[BK][BM + 4];
    __shared__ __align__(16) float Bg[BK][BN + 4];
    __shared__ __align__(16) float Bu[BK][BN + 4];

    int tid = threadIdx.x;
    int tx  = tid & 15;      // 0..15 -> 4 output cols each
    int ty  = tid >> 4;      // 0..15 -> 4 output rows each
    int lr  = tid >> 2;      // 0..63  load row
    int lk  = (tid & 3) * 4; // 0,4,8,12 load k-chunk

    int row = mb * BM + lr;
    int tok = g_tok[e * TT + (row < cnt ? row : cnt - 1)];
    const float* arow = x + (size_t)tok * HH;

    const float* w13e  = w13 + (size_t)e * (2 * (size_t)II) * HH;
    const float* bgrow = w13e + (size_t)(nb * BN + lr) * HH;
    const float* burow = w13e + ((size_t)II + nb * BN + lr) * HH;

    float accg[4][4] = {{0.f}}, accu[4][4] = {{0.f}};

    for (int k0 = 0; k0 < HH; k0 += BK) {
        float4 av = *(const float4*)&arow[k0 + lk];
        float4 gv = *(const float4*)&bgrow[k0 + lk];
        float4 uv = *(const float4*)&burow[k0 + lk];
        __syncthreads();
        As[lk + 0][lr] = av.x; As[lk + 1][lr] = av.y; As[lk + 2][lr] = av.z; As[lk + 3][lr] = av.w;
        Bg[lk + 0][lr] = gv.x; Bg[lk + 1][lr] = gv.y; Bg[lk + 2][lr] = gv.z; Bg[lk + 3][lr] = gv.w;
        Bu[lk + 0][lr] = uv.x; Bu[lk + 1][lr] = uv.y; Bu[lk + 2][lr] = uv.z; Bu[lk + 3][lr] = uv.w;
        __syncthreads();
#pragma unroll
        for (int k = 0; k < BK; k++) {
            float af[4], gf[4], uf[4];
            *(float4*)af = *(const float4*)&As[k][ty * 4];
            *(float4*)gf = *(const float4*)&Bg[k][tx * 4];
            *(float4*)uf = *(const float4*)&Bu[k][tx * 4];
#pragma unroll
            for (int i = 0; i < 4; i++) {
#pragma unroll
                for (int j = 0; j < 4; j++) {
                    accg[i][j] += af[i] * gf[j];
                    accu[i][j] += af[i] * uf[j];
                }
            }
        }
    }

    float* hbase = g_h + (size_t)e * TT * II;
#pragma unroll
    for (int i = 0; i < 4; i++) {
        int r = mb * BM + ty * 4 + i;
        if (r < cnt) {
            float4 hv;
            float s;
            s = accg[i][0]; hv.x = s / (1.f + expf(-s)) * accu[i][0];
            s = accg[i][1]; hv.y = s / (1.f + expf(-s)) * accu[i][1];
            s = accg[i][2]; hv.z = s / (1.f + expf(-s)) * accu[i][2];
            s = accg[i][3]; hv.w = s / (1.f + expf(-s)) * accu[i][3];
            *(float4*)&hbase[(size_t)r * II + nb * BN + tx * 4] = hv;
        }
    }
}

// ---------------- kernel 4: GEMM2  y = h @ w2^T ----------------
// grid: (HH/BN, TT/BM, EE); block 256
__global__ void __launch_bounds__(256) gemm2_kernel(const float* __restrict__ w2)
{
    int e   = blockIdx.z;
    int cnt = g_cnt[e];
    int mb  = blockIdx.y;
    if (mb * BM >= cnt) return;
    int nb = blockIdx.x;

    __shared__ __align__(16) float As[BK][BM + 4];
    __shared__ __align__(16) float Bs[BK][BN + 4];

    int tid = threadIdx.x;
    int tx  = tid & 15;
    int ty  = tid >> 4;
    int lr  = tid >> 2;
    int lk  = (tid & 3) * 4;

    int row = mb * BM + lr;
    const float* arow = g_h + ((size_t)e * TT + (row < cnt ? row : cnt - 1)) * II;
    const float* brow = w2 + ((size_t)e * HH + nb * BN + lr) * II;

    float acc[4][4] = {{0.f}};

    for (int k0 = 0; k0 < II; k0 += BK) {
        float4 av = *(const float4*)&arow[k0 + lk];
        float4 bv = *(const float4*)&brow[k0 + lk];
        __syncthreads();
        As[lk + 0][lr] = av.x; As[lk + 1][lr] = av.y; As[lk + 2][lr] = av.z; As[lk + 3][lr] = av.w;
        Bs[lk + 0][lr] = bv.x; Bs[lk + 1][lr] = bv.y; Bs[lk + 2][lr] = bv.z; Bs[lk + 3][lr] = bv.w;
        __syncthreads();
#pragma unroll
        for (int k = 0; k < BK; k++) {
            float af[4], bf[4];
            *(float4*)af = *(const float4*)&As[k][ty * 4];
            *(float4*)bf = *(const float4*)&Bs[k][tx * 4];
#pragma unroll
            for (int i = 0; i < 4; i++) {
#pragma unroll
                for (int j = 0; j < 4; j++)
                    acc[i][j] += af[i] * bf[j];
            }
        }
    }

    float* ybase = g_y + (size_t)e * TT * HH;
#pragma unroll
    for (int i = 0; i < 4; i++) {
        int r = mb * BM + ty * 4 + i;
        if (r < cnt) {
            float4 ov;
            ov.x = acc[i][0]; ov.y = acc[i][1]; ov.z = acc[i][2]; ov.w = acc[i][3];
            *(float4*)&ybase[(size_t)r * HH + nb * BN + tx * 4] = ov;
        }
    }
}

// ---------------- kernel 5: weighted combine ----------------
__global__ void combine_kernel(float* __restrict__ out) {
    int idx = blockIdx.x * blockDim.x + threadIdx.x;   // over TT*HH/4
    int t = idx / (HH / 4);
    int c = (idx % (HH / 4)) * 4;
    float w0 = g_wt[t * 2 + 0];
    float w1 = g_wt[t * 2 + 1];
    const float4 y0 = *(const float4*)&g_y[(size_t)g_slot[t * 2 + 0] * HH + c];
    const float4 y1 = *(const float4*)&g_y[(size_t)g_slot[t * 2 + 1] * HH + c];
    float4 o;
    o.x = w0 * y0.x + w1 * y1.x;
    o.y = w0 * y0.y + w1 * y1.y;
    o.z = w0 * y0.z + w1 * y1.z;
    o.w = w0 * y0.w + w1 * y1.w;
    *(float4*)&out[(size_t)t * HH + c] = o;
}

// ---------------- launch ----------------
extern "C" void kernel_launch(void* const* d_in, const int* in_sizes, int n_in,
                              void* d_out, int out_size)
{
    const float* x   = (const float*)d_in[0];   // hidden_states (T,H)
    const float* gw  = (const float*)d_in[1];   // gate_w (E,H)
    const float* w13 = (const float*)d_in[2];   // (E, 2I, H)
    const float* w2  = (const float*)d_in[3];   // (E, H, I)
    (void)in_sizes; (void)n_in; (void)out_size; // top_k fixed at 2

    zero_counts_kernel<<<1, 32>>>();
    gate_kernel<<<TT / 4, 128>>>(x, gw);
    gemm1_kernel<<<dim3(II / BN, TT / BM, EE), 256>>>(x, w13);
    gemm2_kernel<<<dim3(HH / BN, TT / BM, EE), 256>>>(w2);
    combine_kernel<<<(TT * HH / 4) / 256, 256>>>((float*)d_out);
}

// round 11
// speedup vs baseline: 2.7161x; 2.7161x over previous
#include <cuda_runtime.h>
#include <cuda_bf16.h>
#include <cstdint>
#include <math.h>

#define TT 4096
#define HH 2048
#define EE 8
#define II 5632

// ---------------- static device scratch ----------------
__device__ int   g_cnt[EE];
__device__ int   g_tok[EE * TT];
__device__ int   g_slot[TT * 2];
__device__ float g_wt[TT * 2];
__device__ float g_h[(size_t)EE * TT * II];     // silu(g)*u intermediate
__device__ float g_y[(size_t)EE * TT * HH];     // per-(expert,pos) outputs

// ---------------- helpers ----------------
__device__ __forceinline__ uint32_t smem_u32(const void* p) {
    uint32_t a;
    asm("{ .reg .u64 t; cvta.to.shared.u64 t, %1; cvt.u32.u64 %0, t; }" : "=r"(a) : "l"(p));
    return a;
}

__device__ __forceinline__ void mma_bf16(float* c, const uint32_t* a, const uint32_t* b) {
    asm volatile(
        "mma.sync.aligned.m16n8k16.row.col.f32.bf16.bf16.f32 "
        "{%0,%1,%2,%3}, {%4,%5,%6,%7}, {%8,%9}, {%0,%1,%2,%3};\n"
        : "+f"(c[0]), "+f"(c[1]), "+f"(c[2]), "+f"(c[3])
        : "r"(a[0]), "r"(a[1]), "r"(a[2]), "r"(a[3]), "r"(b[0]), "r"(b[1]));
}
__device__ __forceinline__ void ldsm_x4(uint32_t* d, uint32_t addr) {
    asm volatile("ldmatrix.sync.aligned.m8n8.x4.shared.b16 {%0,%1,%2,%3}, [%4];"
        : "=r"(d[0]), "=r"(d[1]), "=r"(d[2]), "=r"(d[3]) : "r"(addr));
}
__device__ __forceinline__ void ldsm_x2(uint32_t* d, uint32_t addr) {
    asm volatile("ldmatrix.sync.aligned.m8n8.x2.shared.b16 {%0,%1}, [%2];"
        : "=r"(d[0]), "=r"(d[1]) : "r"(addr));
}
// split float4 into bf16-hi pack and bf16-lo (residual) pack
__device__ __forceinline__ void split_f4(float4 v, uint2& hp, uint2& lp) {
    __nv_bfloat162 h01 = __floats2bfloat162_rn(v.x, v.y);
    __nv_bfloat162 h23 = __floats2bfloat162_rn(v.z, v.w);
    float r0 = v.x - __bfloat162float(h01.x);
    float r1 = v.y - __bfloat162float(h01.y);
    float r2 = v.z - __bfloat162float(h23.x);
    float r3 = v.w - __bfloat162float(h23.y);
    __nv_bfloat162 l01 = __floats2bfloat162_rn(r0, r1);
    __nv_bfloat162 l23 = __floats2bfloat162_rn(r2, r3);
    hp.x = *(uint32_t*)&h01; hp.y = *(uint32_t*)&h23;
    lp.x = *(uint32_t*)&l01; lp.y = *(uint32_t*)&l23;
}

// smem tile geometry: 128 rows x 32 bf16, padded row stride 40 elems (80 B)
#define ROWB 80
#define TILE_SZ (128 * ROWB)   // 10240 B per tile

// ---------------- kernel 1: zero counters ----------------
__global__ void zero_counts_kernel() {
    if (threadIdx.x < EE) g_cnt[threadIdx.x] = 0;
}

// ---------------- kernel 2: gating ----------------
__global__ void gate_kernel(const float* __restrict__ x, const float* __restrict__ gw) {
    int tid = threadIdx.x, warp = tid >> 5, lane = tid & 31;
    int t = blockIdx.x * 4 + warp;
    if (t >= TT) return;
    const float* xr = x + (size_t)t * HH;
    float acc[EE];
#pragma unroll
    for (int e = 0; e < EE; e++) acc[e] = 0.f;
    for (int h0 = lane * 4; h0 < HH; h0 += 128) {
        float4 xv = *(const float4*)&xr[h0];
#pragma unroll
        for (int e = 0; e < EE; e++) {
            float4 wv = __ldg((const float4*)&gw[e * HH + h0]);
            acc[e] += xv.x * wv.x + xv.y * wv.y + xv.z * wv.z + xv.w * wv.w;
        }
    }
#pragma unroll
    for (int off = 16; off; off >>= 1)
#pragma unroll
        for (int e = 0; e < EE; e++) acc[e] += __shfl_xor_sync(0xffffffffu, acc[e], off);
    if (lane == 0) {
        int e0 = 0;
#pragma unroll
        for (int e = 1; e < EE; e++) if (acc[e] > acc[e0]) e0 = e;
        int e1 = (e0 == 0) ? 1 : 0;
#pragma unroll
        for (int e = 0; e < EE; e++) if (e != e0 && acc[e] > acc[e1]) e1 = e;
        float p1 = expf(acc[e1] - acc[e0]);
        float w0 = 1.f / (1.f + p1);
        float w1 = p1 * w0;
        int pos0 = atomicAdd(&g_cnt[e0], 1);
        int pos1 = atomicAdd(&g_cnt[e1], 1);
        g_tok[e0 * TT + pos0] = t;
        g_tok[e1 * TT + pos1] = t;
        g_slot[t * 2 + 0] = e0 * TT + pos0;
        g_slot[t * 2 + 1] = e1 * TT + pos1;
        g_wt[t * 2 + 0] = w0;
        g_wt[t * 2 + 1] = w1;
    }
}

// ---------------- 3xBF16 mma.sync GEMM ----------------
// G1: h = silu(X @ Wg^T) * (X @ Wu^T), gate/up interleaved as even/odd B rows.
// G0: y = h @ w2^T.
// CTA: 128(M) x 128(N), K-step 32. 8 warps as 2(m) x 4(n); warp tile 64x32.
template<int G1>
__global__ void __launch_bounds__(256, 1) moe_mma_kernel(
    const float* __restrict__ x, const float* __restrict__ w13, const float* __restrict__ w2)
{
    __shared__ __align__(16) uint8_t smBuf[4][TILE_SZ];   // Ahi, Alo, Bhi, Blo

    int e = blockIdx.z, mb = blockIdx.y, nb = blockIdx.x;
    int cnt = g_cnt[e];
    if (mb * 128 >= cnt) return;

    int tid = threadIdx.x, wid = tid >> 5, lane = tid & 31;
    int wm = wid >> 2, wn = wid & 3;   // warp grid 2 x 4

    uint32_t sA_hi = smem_u32(&smBuf[0][0]);
    uint32_t sA_lo = smem_u32(&smBuf[1][0]);
    uint32_t sB_hi = smem_u32(&smBuf[2][0]);
    uint32_t sB_lo = smem_u32(&smBuf[3][0]);

    // per-thread gmem row pointers (4 rows each for A and B), fixed k-quad
    const int kq4 = (tid & 7) * 4;           // float col within 32-wide k step
    const float* ap[4];
    const float* bp[4];
#pragma unroll
    for (int j = 0; j < 4; j++) {
        int r = (tid >> 3) + 32 * j;         // 0..127
        if (G1) {
            int idx = mb * 128 + r;
            if (idx >= cnt) idx = cnt - 1;
            ap[j] = x + (size_t)g_tok[e * TT + idx] * HH;
            const float* w13e = w13 + (size_t)e * (2 * (size_t)II) * HH;
            int neuron = nb * 64 + (r >> 1);
            bp[j] = w13e + ((size_t)((r & 1) ? II + neuron : neuron)) * HH;
        } else {
            ap[j] = g_h + ((size_t)e * TT + mb * 128 + r) * II;
            bp[j] = w2 + ((size_t)e * HH + nb * 128 + r) * II;
        }
    }
    // smem store byte offsets (4 bf16 = 8 B per quad)
    uint32_t sto[4];
#pragma unroll
    for (int j = 0; j < 4; j++)
        sto[j] = (uint32_t)(((tid >> 3) + 32 * j) * ROWB + (tid & 7) * 8);

    // ldmatrix per-lane offsets
    uint32_t a_lane = (uint32_t)(((lane & 7) + ((lane >> 3) & 1) * 8) * ROWB + (lane >> 4) * 16);
    uint32_t b_lane = (uint32_t)((lane & 7) * ROWB + ((lane >> 3) & 1) * 16);

    float acc[4][4][4];
#pragma unroll
    for (int im = 0; im < 4; im++)
#pragma unroll
        for (int in = 0; in < 4; in++)
#pragma unroll
            for (int q = 0; q < 4; q++) acc[im][in][q] = 0.f;

    const int K = G1 ? HH : II;
    const int nst = K / 32;

    float4 aReg[4], bReg[4];
#pragma unroll
    for (int j = 0; j < 4; j++) {
        aReg[j] = __ldg((const float4*)(ap[j] + kq4));
        bReg[j] = __ldg((const float4*)(bp[j] + kq4));
    }

    for (int i = 0; i < nst; i++) {
        __syncthreads();   // previous stage fully consumed
#pragma unroll
        for (int j = 0; j < 4; j++) {
            uint2 hp, lp;
            split_f4(aReg[j], hp, lp);
            *(uint2*)&smBuf[0][sto[j]] = hp;
            *(uint2*)&smBuf[1][sto[j]] = lp;
            split_f4(bReg[j], hp, lp);
            *(uint2*)&smBuf[2][sto[j]] = hp;
            *(uint2*)&smBuf[3][sto[j]] = lp;
        }
        __syncthreads();
        if (i + 1 < nst) {
            int k0 = (i + 1) * 32 + kq4;
#pragma unroll
            for (int j = 0; j < 4; j++) {
                aReg[j] = __ldg((const float4*)(ap[j] + k0));
                bReg[j] = __ldg((const float4*)(bp[j] + k0));
            }
        }
        // consume stage: two k16 sub-steps
#pragma unroll
        for (int kk = 0; kk < 2; kk++) {
            uint32_t koff = (uint32_t)(kk * 32);  // 16 bf16 = 32 B
            uint32_t bh[4][2], bl[4][2];
#pragma unroll
            for (int in = 0; in < 4; in++) {
                uint32_t boff = (uint32_t)((wn * 32 + in * 8) * ROWB) + koff + b_lane;
                ldsm_x2(bh[in], sB_hi + boff);
                ldsm_x2(bl[in], sB_lo + boff);
            }
#pragma unroll
            for (int im = 0; im < 4; im++) {
                uint32_t aoff = (uint32_t)((wm * 64 + im * 16) * ROWB) + koff + a_lane;
                uint32_t ah[4], al[4];
                ldsm_x4(ah, sA_hi + aoff);
                ldsm_x4(al, sA_lo + aoff);
#pragma unroll
                for (int in = 0; in < 4; in++) {
                    mma_bf16(acc[im][in], ah, bh[in]);
                    mma_bf16(acc[im][in], ah, bl[in]);
                    mma_bf16(acc[im][in], al, bh[in]);
                }
            }
        }
    }

    // ---------------- epilogue ----------------
    int rbase = mb * 128 + wm * 64 + (lane >> 2);
    if (G1) {
        // acc cols alternate gate(even)/up(odd); thread pair (c0,c1)=(g,u), (c2,c3) row+8
#pragma unroll
        for (int im = 0; im < 4; im++) {
            int r0 = rbase + im * 16;
#pragma unroll
            for (int in = 0; in < 4; in++) {
                int hcol = nb * 64 + wn * 16 + in * 4 + (lane & 3);
                float g0 = acc[im][in][0], u0 = acc[im][in][1];
                float g1 = acc[im][in][2], u1 = acc[im][in][3];
                if (r0 < cnt)
                    g_h[((size_t)e * TT + r0) * II + hcol] = g0 / (1.f + expf(-g0)) * u0;
                if (r0 + 8 < cnt)
                    g_h[((size_t)e * TT + r0 + 8) * II + hcol] = g1 / (1.f + expf(-g1)) * u1;
            }
        }
    } else {
#pragma unroll
        for (int im = 0; im < 4; im++) {
            int r0 = rbase + im * 16;
#pragma unroll
            for (int in = 0; in < 4; in++) {
                int col = nb * 128 + wn * 32 + in * 8 + 2 * (lane & 3);
                if (r0 < cnt)
                    *(float2*)&g_y[((size_t)e * TT + r0) * HH + col] =
                        make_float2(acc[im][in][0], acc[im][in][1]);
                if (r0 + 8 < cnt)
                    *(float2*)&g_y[((size_t)e * TT + r0 + 8) * HH + col] =
                        make_float2(acc[im][in][2], acc[im][in][3]);
            }
        }
    }
}

// ---------------- kernel 5: weighted combine ----------------
__global__ void combine_kernel(float* __restrict__ out) {
    int idx = blockIdx.x * blockDim.x + threadIdx.x;
    int t = idx / (HH / 4);
    int c = (idx % (HH / 4)) * 4;
    float w0 = g_wt[t * 2 + 0];
    float w1 = g_wt[t * 2 + 1];
    const float4 y0 = *(const float4*)&g_y[(size_t)g_slot[t * 2 + 0] * HH + c];
    const float4 y1 = *(const float4*)&g_y[(size_t)g_slot[t * 2 + 1] * HH + c];
    float4 o;
    o.x = w0 * y0.x + w1 * y1.x;
    o.y = w0 * y0.y + w1 * y1.y;
    o.z = w0 * y0.z + w1 * y1.z;
    o.w = w0 * y0.w + w1 * y1.w;
    *(float4*)&out[(size_t)t * HH + c] = o;
}

// ---------------- launch ----------------
extern "C" void kernel_launch(void* const* d_in, const int* in_sizes, int n_in,
                              void* d_out, int out_size)
{
    const float* x   = (const float*)d_in[0];
    const float* gw  = (const float*)d_in[1];
    const float* w13 = (const float*)d_in[2];
    const float* w2  = (const float*)d_in[3];
    (void)in_sizes; (void)n_in; (void)out_size;

    zero_counts_kernel<<<1, 32>>>();
    gate_kernel<<<TT / 4, 128>>>(x, gw);
    // GEMM1: N covers 2I interleaved as 64 (gate,up) pairs per CTA -> 2*II/128 = 88 tiles
    moe_mma_kernel<1><<<dim3(2 * II / 128, TT / 128, EE), 256>>>(x, w13, w2);
    // GEMM2: N covers H -> 16 tiles
    moe_mma_kernel<0><<<dim3(HH / 128, TT / 128, EE), 256>>>(x, w13, w2);
    combine_kernel<<<(TT * HH / 4) / 256, 256>>>((float*)d_out);
}

// round 13
// speedup vs baseline: 2.7751x; 1.0217x over previous
#include <cuda_runtime.h>
#include <cuda_bf16.h>
#include <cstdint>
#include <math.h>

#define TT 4096
#define HH 2048
#define EE 8
#define II 5632

// ---------------- static device scratch ----------------
__device__ int   g_cnt[EE];
__device__ int   g_tok[EE * TT];
__device__ int   g_slot[TT * 2];
__device__ float g_wt[TT * 2];
__device__ float g_h[(size_t)EE * TT * II];     // silu(g)*u intermediate
__device__ float g_y[(size_t)EE * TT * HH];     // per-(expert,pos) outputs

// ---------------- helpers ----------------
__device__ __forceinline__ uint32_t smem_u32(const void* p) {
    uint32_t a;
    asm("{ .reg .u64 t; cvta.to.shared.u64 t, %1; cvt.u32.u64 %0, t; }" : "=r"(a) : "l"(p));
    return a;
}

__device__ __forceinline__ void mma_bf16(float* c, const uint32_t* a, const uint32_t* b) {
    asm volatile(
        "mma.sync.aligned.m16n8k16.row.col.f32.bf16.bf16.f32 "
        "{%0,%1,%2,%3}, {%4,%5,%6,%7}, {%8,%9}, {%0,%1,%2,%3};\n"
        : "+f"(c[0]), "+f"(c[1]), "+f"(c[2]), "+f"(c[3])
        : "r"(a[0]), "r"(a[1]), "r"(a[2]), "r"(a[3]), "r"(b[0]), "r"(b[1]));
}
__device__ __forceinline__ void ldsm_x4(uint32_t* d, uint32_t addr) {
    asm volatile("ldmatrix.sync.aligned.m8n8.x4.shared.b16 {%0,%1,%2,%3}, [%4];"
        : "=r"(d[0]), "=r"(d[1]), "=r"(d[2]), "=r"(d[3]) : "r"(addr));
}
__device__ __forceinline__ void ldsm_x2(uint32_t* d, uint32_t addr) {
    asm volatile("ldmatrix.sync.aligned.m8n8.x2.shared.b16 {%0,%1}, [%2];"
        : "=r"(d[0]), "=r"(d[1]) : "r"(addr));
}
// split float4 into bf16-hi pack and bf16-lo (residual) pack
__device__ __forceinline__ void split_f4(float4 v, uint2& hp, uint2& lp) {
    __nv_bfloat162 h01 = __floats2bfloat162_rn(v.x, v.y);
    __nv_bfloat162 h23 = __floats2bfloat162_rn(v.z, v.w);
    float r0 = v.x - __bfloat162float(h01.x);
    float r1 = v.y - __bfloat162float(h01.y);
    float r2 = v.z - __bfloat162float(h23.x);
    float r3 = v.w - __bfloat162float(h23.y);
    __nv_bfloat162 l01 = __floats2bfloat162_rn(r0, r1);
    __nv_bfloat162 l23 = __floats2bfloat162_rn(r2, r3);
    hp.x = *(uint32_t*)&h01; hp.y = *(uint32_t*)&h23;
    lp.x = *(uint32_t*)&l01; lp.y = *(uint32_t*)&l23;
}

// smem tile geometry: 128 rows x 32 bf16, padded row stride 40 elems (80 B)
#define ROWB 80
#define TILE_SZ (128 * ROWB)       // 10240 B per tile
#define STAGE_SZ (4 * TILE_SZ)     // Ahi, Alo, Bhi, Blo
#define SMEM_DYN (2 * STAGE_SZ)    // 81920 B, double-buffered

// ---------------- kernel 1: zero counters ----------------
__global__ void zero_counts_kernel() {
    if (threadIdx.x < EE) g_cnt[threadIdx.x] = 0;
}

// ---------------- kernel 2: gating ----------------
__global__ void gate_kernel(const float* __restrict__ x, const float* __restrict__ gw) {
    int tid = threadIdx.x, warp = tid >> 5, lane = tid & 31;
    int t = blockIdx.x * 4 + warp;
    if (t >= TT) return;
    const float* xr = x + (size_t)t * HH;
    float acc[EE];
#pragma unroll
    for (int e = 0; e < EE; e++) acc[e] = 0.f;
    for (int h0 = lane * 4; h0 < HH; h0 += 128) {
        float4 xv = *(const float4*)&xr[h0];
#pragma unroll
        for (int e = 0; e < EE; e++) {
            float4 wv = __ldg((const float4*)&gw[e * HH + h0]);
            acc[e] += xv.x * wv.x + xv.y * wv.y + xv.z * wv.z + xv.w * wv.w;
        }
    }
#pragma unroll
    for (int off = 16; off; off >>= 1)
#pragma unroll
        for (int e = 0; e < EE; e++) acc[e] += __shfl_xor_sync(0xffffffffu, acc[e], off);
    if (lane == 0) {
        int e0 = 0;
#pragma unroll
        for (int e = 1; e < EE; e++) if (acc[e] > acc[e0]) e0 = e;
        int e1 = (e0 == 0) ? 1 : 0;
#pragma unroll
        for (int e = 0; e < EE; e++) if (e != e0 && acc[e] > acc[e1]) e1 = e;
        float p1 = expf(acc[e1] - acc[e0]);
        float w0 = 1.f / (1.f + p1);
        float w1 = p1 * w0;
        int pos0 = atomicAdd(&g_cnt[e0], 1);
        int pos1 = atomicAdd(&g_cnt[e1], 1);
        g_tok[e0 * TT + pos0] = t;
        g_tok[e1 * TT + pos1] = t;
        g_slot[t * 2 + 0] = e0 * TT + pos0;
        g_slot[t * 2 + 1] = e1 * TT + pos1;
        g_wt[t * 2 + 0] = w0;
        g_wt[t * 2 + 1] = w1;
    }
}

// ---------------- 3xBF16 mma.sync GEMM, double-buffered ----------------
// G1: h = silu(X @ Wg^T) * (X @ Wu^T), gate/up interleaved as even/odd B rows.
// G0: y = h @ w2^T.
// CTA: 128(M) x 128(N), K-step 32. 8 warps as 2(m) x 4(n); warp tile 64x32.
template<int G1>
__global__ void __launch_bounds__(256, 1) moe_mma_kernel(
    const float* __restrict__ x, const float* __restrict__ w13, const float* __restrict__ w2)
{
    extern __shared__ __align__(16) uint8_t smBuf[];   // [2 stages][Ahi,Alo,Bhi,Blo]

    int e = blockIdx.z, mb = blockIdx.y, nb = blockIdx.x;
    int cnt = g_cnt[e];
    if (mb * 128 >= cnt) return;

    int tid = threadIdx.x, wid = tid >> 5, lane = tid & 31;
    int wm = wid >> 2, wn = wid & 3;   // warp grid 2 x 4

    uint32_t sbase = smem_u32(smBuf);

    // per-thread gmem row pointers (4 rows each for A and B), fixed k-quad
    const int kq4 = (tid & 7) * 4;           // float col within 32-wide k step
    const float* ap[4];
    const float* bp[4];
#pragma unroll
    for (int j = 0; j < 4; j++) {
        int r = (tid >> 3) + 32 * j;         // 0..127
        if (G1) {
            int idx = mb * 128 + r;
            if (idx >= cnt) idx = cnt - 1;
            ap[j] = x + (size_t)g_tok[e * TT + idx] * HH;
            const float* w13e = w13 + (size_t)e * (2 * (size_t)II) * HH;
            int neuron = nb * 64 + (r >> 1);
            bp[j] = w13e + ((size_t)((r & 1) ? II + neuron : neuron)) * HH;
        } else {
            ap[j] = g_h + ((size_t)e * TT + mb * 128 + r) * II;
            bp[j] = w2 + ((size_t)e * HH + nb * 128 + r) * II;
        }
    }
    // smem store byte offsets (4 bf16 = 8 B per quad)
    uint32_t sto[4];
#pragma unroll
    for (int j = 0; j < 4; j++)
        sto[j] = (uint32_t)(((tid >> 3) + 32 * j) * ROWB + (tid & 7) * 8);

    // ldmatrix per-lane offsets
    uint32_t a_lane = (uint32_t)(((lane & 7) + ((lane >> 3) & 1) * 8) * ROWB + (lane >> 4) * 16);
    uint32_t b_lane = (uint32_t)((lane & 7) * ROWB + ((lane >> 3) & 1) * 16);

    float acc[4][4][4];
#pragma unroll
    for (int im = 0; im < 4; im++)
#pragma unroll
        for (int in = 0; in < 4; in++)
#pragma unroll
            for (int q = 0; q < 4; q++) acc[im][in][q] = 0.f;

    const int K = G1 ? HH : II;
    const int nst = K / 32;

    float4 aReg[4], bReg[4];
#pragma unroll
    for (int j = 0; j < 4; j++) {
        aReg[j] = __ldg((const float4*)(ap[j] + kq4));
        bReg[j] = __ldg((const float4*)(bp[j] + kq4));
    }
    // store tile 0 into stage 0
    {
        uint8_t* st = smBuf;
#pragma unroll
        for (int j = 0; j < 4; j++) {
            uint2 hp, lp;
            split_f4(aReg[j], hp, lp);
            *(uint2*)(st + 0 * TILE_SZ + sto[j]) = hp;
            *(uint2*)(st + 1 * TILE_SZ + sto[j]) = lp;
            split_f4(bReg[j], hp, lp);
            *(uint2*)(st + 2 * TILE_SZ + sto[j]) = hp;
            *(uint2*)(st + 3 * TILE_SZ + sto[j]) = lp;
        }
    }
    __syncthreads();

    for (int i = 0; i < nst; i++) {
        int s = i & 1;
        bool more = (i + 1 < nst);
        if (more) {
            int k0 = (i + 1) * 32 + kq4;
#pragma unroll
            for (int j = 0; j < 4; j++) {
                aReg[j] = __ldg((const float4*)(ap[j] + k0));
                bReg[j] = __ldg((const float4*)(bp[j] + k0));
            }
        }
        // consume stage s: two k16 sub-steps
        uint32_t sA_hi = sbase + (uint32_t)s * STAGE_SZ;
        uint32_t sA_lo = sA_hi + TILE_SZ;
        uint32_t sB_hi = sA_hi + 2 * TILE_SZ;
        uint32_t sB_lo = sA_hi + 3 * TILE_SZ;
#pragma unroll
        for (int kk = 0; kk < 2; kk++) {
            uint32_t koff = (uint32_t)(kk * 32);  // 16 bf16 = 32 B
            uint32_t bh[4][2], bl[4][2];
#pragma unroll
            for (int in = 0; in < 4; in++) {
                uint32_t boff = (uint32_t)((wn * 32 + in * 8) * ROWB) + koff + b_lane;
                ldsm_x2(bh[in], sB_hi + boff);
                ldsm_x2(bl[in], sB_lo + boff);
            }
#pragma unroll
            for (int im = 0; im < 4; im++) {
                uint32_t aoff = (uint32_t)((wm * 64 + im * 16) * ROWB) + koff + a_lane;
                uint32_t ah[4], al[4];
                ldsm_x4(ah, sA_hi + aoff);
                ldsm_x4(al, sA_lo + aoff);
#pragma unroll
                for (int in = 0; in < 4; in++) {
                    mma_bf16(acc[im][in], ah, bh[in]);
                    mma_bf16(acc[im][in], ah, bl[in]);
                    mma_bf16(acc[im][in], al, bh[in]);
                }
            }
        }
        // store tile i+1 into the other stage (no conflict with stage s reads)
        if (more) {
            uint8_t* st = smBuf + (size_t)(s ^ 1) * STAGE_SZ;
#pragma unroll
            for (int j = 0; j < 4; j++) {
                uint2 hp, lp;
                split_f4(aReg[j], hp, lp);
                *(uint2*)(st + 0 * TILE_SZ + sto[j]) = hp;
                *(uint2*)(st + 1 * TILE_SZ + sto[j]) = lp;
                split_f4(bReg[j], hp, lp);
                *(uint2*)(st + 2 * TILE_SZ + sto[j]) = hp;
                *(uint2*)(st + 3 * TILE_SZ + sto[j]) = lp;
            }
        }
        __syncthreads();
    }

    // ---------------- epilogue ----------------
    int rbase = mb * 128 + wm * 64 + (lane >> 2);
    if (G1) {
        // acc cols alternate gate(even)/up(odd); thread pair (c0,c1)=(g,u), (c2,c3) row+8
#pragma unroll
        for (int im = 0; im < 4; im++) {
            int r0 = rbase + im * 16;
#pragma unroll
            for (int in = 0; in < 4; in++) {
                int hcol = nb * 64 + wn * 16 + in * 4 + (lane & 3);
                float g0 = acc[im][in][0], u0 = acc[im][in][1];
                float g1 = acc[im][in][2], u1 = acc[im][in][3];
                if (r0 < cnt)
                    g_h[((size_t)e * TT + r0) * II + hcol] = g0 / (1.f + expf(-g0)) * u0;
                if (r0 + 8 < cnt)
                    g_h[((size_t)e * TT + r0 + 8) * II + hcol] = g1 / (1.f + expf(-g1)) * u1;
            }
        }
    } else {
#pragma unroll
        for (int im = 0; im < 4; im++) {
            int r0 = rbase + im * 16;
#pragma unroll
            for (int in = 0; in < 4; in++) {
                int col = nb * 128 + wn * 32 + in * 8 + 2 * (lane & 3);
                if (r0 < cnt)
                    *(float2*)&g_y[((size_t)e * TT + r0) * HH + col] =
                        make_float2(acc[im][in][0], acc[im][in][1]);
                if (r0 + 8 < cnt)
                    *(float2*)&g_y[((size_t)e * TT + r0 + 8) * HH + col] =
                        make_float2(acc[im][in][2], acc[im][in][3]);
            }
        }
    }
}

// ---------------- kernel 5: weighted combine ----------------
__global__ void combine_kernel(float* __restrict__ out) {
    int idx = blockIdx.x * blockDim.x + threadIdx.x;
    int t = idx / (HH / 4);
    int c = (idx % (HH / 4)) * 4;
    float w0 = g_wt[t * 2 + 0];
    float w1 = g_wt[t * 2 + 1];
    const float4 y0 = *(const float4*)&g_y[(size_t)g_slot[t * 2 + 0] * HH + c];
    const float4 y1 = *(const float4*)&g_y[(size_t)g_slot[t * 2 + 1] * HH + c];
    float4 o;
    o.x = w0 * y0.x + w1 * y1.x;
    o.y = w0 * y0.y + w1 * y1.y;
    o.z = w0 * y0.z + w1 * y1.z;
    o.w = w0 * y0.w + w1 * y1.w;
    *(float4*)&out[(size_t)t * HH + c] = o;
}

// ---------------- launch ----------------
extern "C" void kernel_launch(void* const* d_in, const int* in_sizes, int n_in,
                              void* d_out, int out_size)
{
    const float* x   = (const float*)d_in[0];
    const float* gw  = (const float*)d_in[1];
    const float* w13 = (const float*)d_in[2];
    const float* w2  = (const float*)d_in[3];
    (void)in_sizes; (void)n_in; (void)out_size;

    cudaFuncSetAttribute(moe_mma_kernel<1>, cudaFuncAttributeMaxDynamicSharedMemorySize, SMEM_DYN);
    cudaFuncSetAttribute(moe_mma_kernel<0>, cudaFuncAttributeMaxDynamicSharedMemorySize, SMEM_DYN);

    zero_counts_kernel<<<1, 32>>>();
    gate_kernel<<<TT / 4, 128>>>(x, gw);
    // GEMM1: N covers 2I interleaved as 64 (gate,up) pairs per CTA -> 2*II/128 = 88 tiles
    moe_mma_kernel<1><<<dim3(2 * II / 128, TT / 128, EE), 256, SMEM_DYN>>>(x, w13, w2);
    // GEMM2: N covers H -> 16 tiles
    moe_mma_kernel<0><<<dim3(HH / 128, TT / 128, EE), 256, SMEM_DYN>>>(x, w13, w2);
    combine_kernel<<<(TT * HH / 4) / 256, 256>>>((float*)d_out);
}